// round 10
// baseline (speedup 1.0000x reference)
#include <cuda_runtime.h>

#define BATCH 16
#define CHAN  3
#define HH 512
#define WW 512
#define ROWS_PER_THREAD 4
#define NTHREADS 256
#define DELTA2 1e-6f

__global__ void zero_out_kernel(float* out, int n) {
    int i = blockIdx.x * blockDim.x + threadIdx.x;
    if (i < n) out[i] = 0.0f;
}

// pick element o of {q.x,q.y,q.z,q.w}
__device__ __forceinline__ float sel_q(float4 q, int o) {
    return (o < 2) ? ((o == 0) ? q.x : q.y) : ((o == 2) ? q.z : q.w);
}
// pick element o+1 of {q.x,q.y,q.z,q.w,ex}
__device__ __forceinline__ float sel_q1(float4 q, float ex, int o) {
    return (o < 2) ? ((o == 0) ? q.y : q.z) : ((o == 2) ? q.w : ex);
}

__global__ __launch_bounds__(NTHREADS, 4)   // 1024 thr/SM, 64-reg budget
void photometric_kernel(const float* __restrict__ frame1,
                        const float* __restrict__ frame2,
                        const float* __restrict__ flow,
                        float* __restrict__ out) {
    const int HW = HH * WW;
    const int x  = blockIdx.x * NTHREADS + threadIdx.x;   // lanes: 32 consecutive x
    const int y0 = blockIdx.y * ROWS_PER_THREAD;
    const int b  = blockIdx.z;

    const float* f1b = frame1 + (size_t)b * CHAN * HW;
    const float* f2b = frame2 + (size_t)b * CHAN * HW;
    const float* flx = flow + (size_t)(b * 2 + 0) * HW;
    const float* fly = flow + (size_t)(b * 2 + 1) * HW;
    const float scale = (float)(WW - 1) / (float)WW;      // W == H
    const float xf = (float)x;

    // ---- phase 1: flow loads + coords (independent chains) ----
    int idx00[ROWS_PER_THREAD];
    float wxa[ROWS_PER_THREAD], wya[ROWS_PER_THREAD];

    #pragma unroll
    for (int r = 0; r < ROWS_PER_THREAD; r++) {
        const int y  = y0 + r;
        const int hw = y * WW + x;
        const float fx = __ldg(flx + hw);
        const float fy = __ldg(fly + hw);

        float ix = (xf + fx) * scale;
        float iy = ((float)y + fy) * scale;
        ix = fminf(fmaxf(ix, 0.0f), (float)(WW - 1));
        iy = fminf(fmaxf(iy, 0.0f), (float)(HH - 1));

        const int x0 = min((int)ix, WW - 2);
        const int yi = min((int)iy, HH - 2);
        wxa[r] = ix - (float)x0;
        wya[r] = iy - (float)yi;
        idx00[r] = yi * WW + x0;
    }

    // ---- phase 2: merged float4 gathers + math ----
    float acc = 0.0f;

    #pragma unroll
    for (int r = 0; r < ROWS_PER_THREAD; r++) {
        const int hw  = (y0 + r) * WW + x;
        const int i00 = idx00[r];
        const float wx = wxa[r];
        const float wy = wya[r];
        const int a = i00 & ~3;       // 16B-aligned, same row as i00 (W%4==0)
        const int o = i00 & 3;

        #pragma unroll
        for (int c = 0; c < CHAN; c++) {
            const float* p = f2b + (size_t)c * HW;
            const float4 q0 = __ldg((const float4*)(p + a));        // row y0: covers x0..a+3
            const float4 q1 = __ldg((const float4*)(p + a + WW));   // row y0+1
            float ex0 = 0.0f, ex1 = 0.0f;
            if (o == 3) {                                           // x0+1 == a+4 (25% of lanes)
                ex0 = __ldg(p + i00 + 1);
                ex1 = __ldg(p + i00 + WW + 1);
            }
            const float v00 = sel_q (q0, o);
            const float v01 = sel_q1(q0, ex0, o);
            const float v10 = sel_q (q1, o);
            const float v11 = sel_q1(q1, ex1, o);
            const float top = fmaf(v01 - v00, wx, v00);
            const float bot = fmaf(v11 - v10, wx, v10);
            const float wv  = fmaf(bot - top, wy, top);
            const float d = __ldg(f1b + c * HW + hw) - wv;
            acc += __powf(fmaf(d, d, DELTA2), 0.45f);
        }
    }

    // ---- block reduction ----
    #pragma unroll
    for (int off = 16; off > 0; off >>= 1)
        acc += __shfl_down_sync(0xFFFFFFFFu, acc, off);

    __shared__ float warp_sums[NTHREADS / 32];
    const int lane = threadIdx.x & 31;
    const int wid  = threadIdx.x >> 5;
    if (lane == 0) warp_sums[wid] = acc;
    __syncthreads();

    if (wid == 0) {
        float s = (lane < (NTHREADS / 32)) ? warp_sums[lane] : 0.0f;
        #pragma unroll
        for (int off = 4; off > 0; off >>= 1)
            s += __shfl_down_sync(0xFFFFFFFFu, s, off);
        if (lane == 0) atomicAdd(out, s);
    }
}

extern "C" void kernel_launch(void* const* d_in, const int* in_sizes, int n_in,
                              void* d_out, int out_size) {
    const float* frame1 = (const float*)d_in[0];
    const float* frame2 = (const float*)d_in[1];
    const float* flow   = (const float*)d_in[2];
    float* out = (float*)d_out;

    zero_out_kernel<<<(out_size + 255) / 256, 256>>>(out, out_size);

    dim3 grid(WW / NTHREADS, HH / ROWS_PER_THREAD, BATCH);  // 2 x 128 x 16
    photometric_kernel<<<grid, NTHREADS>>>(frame1, frame2, flow, out);
}

// round 13
// speedup vs baseline: 1.5720x; 1.5720x over previous
#include <cuda_runtime.h>

#define BATCH 16
#define CHAN  3
#define HH 512
#define WW 512
#define ROWS_PER_THREAD 4
#define NTHREADS 128
#define DELTA2 1e-6f

__global__ void zero_out_kernel(float* out, int n) {
    int i = blockIdx.x * blockDim.x + threadIdx.x;
    if (i < n) out[i] = 0.0f;
}

__global__ __launch_bounds__(NTHREADS, 6)   // 768 thr/SM -> ~85-reg budget
void photometric_kernel(const float* __restrict__ frame1,
                        const float* __restrict__ frame2,
                        const float* __restrict__ flow,
                        float* __restrict__ out) {
    const int HW = HH * WW;
    const int x  = blockIdx.x * NTHREADS + threadIdx.x;   // lanes: 32 consecutive x
    const int y0 = blockIdx.y * ROWS_PER_THREAD;
    const int b  = blockIdx.z;

    const float* f1b = frame1 + (size_t)b * CHAN * HW;
    const float* f2b = frame2 + (size_t)b * CHAN * HW;
    const float* flx = flow + (size_t)(b * 2 + 0) * HW;
    const float* fly = flow + (size_t)(b * 2 + 1) * HW;
    const float scale = (float)(WW - 1) / (float)WW;      // W == H
    const float xf = (float)x;

    // ---- phase 1: ALL coalesced loads (flow + frame1) + coords up front ----
    int   idx00[ROWS_PER_THREAD];
    float wxa[ROWS_PER_THREAD], wya[ROWS_PER_THREAD];
    float f1v[ROWS_PER_THREAD][CHAN];

    #pragma unroll
    for (int r = 0; r < ROWS_PER_THREAD; r++) {
        const int y  = y0 + r;
        const int hw = y * WW + x;
        const float fx = __ldg(flx + hw);
        const float fy = __ldg(fly + hw);

        #pragma unroll
        for (int c = 0; c < CHAN; c++)
            f1v[r][c] = __ldg(f1b + c * HW + hw);

        float ix = (xf + fx) * scale;
        float iy = ((float)y + fy) * scale;
        ix = fminf(fmaxf(ix, 0.0f), (float)(WW - 1));
        iy = fminf(fmaxf(iy, 0.0f), (float)(HH - 1));

        // x0 = min(floor(ix), W-2); wx = ix - x0 (exact incl. boundary)
        const int x0 = min((int)ix, WW - 2);
        const int yi = min((int)iy, HH - 2);
        wxa[r] = ix - (float)x0;
        wya[r] = iy - (float)yi;
        idx00[r] = yi * WW + x0;
    }

    // ---- phase 2: scattered LDG.32 gathers (proven fastest form) + math ----
    float acc = 0.0f;

    #pragma unroll
    for (int r = 0; r < ROWS_PER_THREAD; r++) {
        const int i00 = idx00[r];
        const float wx = wxa[r];
        const float wy = wya[r];

        #pragma unroll
        for (int c = 0; c < CHAN; c++) {
            const float* p = f2b + (size_t)c * HW + i00;
            const float v00 = __ldg(p);
            const float v01 = __ldg(p + 1);
            const float v10 = __ldg(p + WW);
            const float v11 = __ldg(p + WW + 1);
            const float top = fmaf(v01 - v00, wx, v00);
            const float bot = fmaf(v11 - v10, wx, v10);
            const float wv  = fmaf(bot - top, wy, top);
            const float d = f1v[r][c] - wv;
            acc += __powf(fmaf(d, d, DELTA2), 0.45f);
        }
    }

    // ---- block reduction ----
    #pragma unroll
    for (int off = 16; off > 0; off >>= 1)
        acc += __shfl_down_sync(0xFFFFFFFFu, acc, off);

    __shared__ float warp_sums[NTHREADS / 32];
    const int lane = threadIdx.x & 31;
    const int wid  = threadIdx.x >> 5;
    if (lane == 0) warp_sums[wid] = acc;
    __syncthreads();

    if (wid == 0) {
        float s = (lane < (NTHREADS / 32)) ? warp_sums[lane] : 0.0f;
        #pragma unroll
        for (int off = 2; off > 0; off >>= 1)
            s += __shfl_down_sync(0xFFFFFFFFu, s, off);
        if (lane == 0) atomicAdd(out, s);
    }
}

extern "C" void kernel_launch(void* const* d_in, const int* in_sizes, int n_in,
                              void* d_out, int out_size) {
    const float* frame1 = (const float*)d_in[0];
    const float* frame2 = (const float*)d_in[1];
    const float* flow   = (const float*)d_in[2];
    float* out = (float*)d_out;

    zero_out_kernel<<<(out_size + 255) / 256, 256>>>(out, out_size);

    dim3 grid(WW / NTHREADS, HH / ROWS_PER_THREAD, BATCH);  // 4 x 128 x 16
    photometric_kernel<<<grid, NTHREADS>>>(frame1, frame2, flow, out);
}